// round 17
// baseline (speedup 1.0000x reference)
#include <cuda_runtime.h>

// RNN_64501818851829 — GB300 sm_103a. Round 17.
// = Round 16 (762us) with the register weight slice extended to k=0..19
//   (100 floats): shared-weight stages 6 -> 5, weight LDS 30 -> 25/step.
//   Topology unchanged: 1024 warp-blocks x 32 thr, 4 rows, fused one-GEMV
//   recurrence (a(t)=lrelu(W1u u + M a(t-1) + c), M=W1h W2), depth-2
//   pipeline on the shared part, one syncwarp/step.

typedef unsigned long long u64;

static constexpr int Tn = 1024;
static constexpr int NTHR = 32;
static constexpr int NBLK = 1024;          // 4 rows per block

__device__ __forceinline__ u64 fma2(u64 a, u64 b, u64 c) {
    u64 d; asm("fma.rn.f32x2 %0, %1, %2, %3;" : "=l"(d) : "l"(a), "l"(b), "l"(c));
    return d;
}
__device__ __forceinline__ u64 add2(u64 a, u64 b) {
    u64 d; asm("add.rn.f32x2 %0, %1, %2;" : "=l"(d) : "l"(a), "l"(b));
    return d;
}
__device__ __forceinline__ u64 mul2(u64 a, u64 b) {
    u64 d; asm("mul.rn.f32x2 %0, %1, %2;" : "=l"(d) : "l"(a), "l"(b));
    return d;
}
__device__ __forceinline__ u64 pack2(float lo, float hi) {
    u64 d; asm("mov.b64 %0, {%1, %2};" : "=l"(d) : "f"(lo), "f"(hi));
    return d;
}
__device__ __forceinline__ void unpack2(u64 v, float& lo, float& hi) {
    asm("mov.b64 {%0, %1}, %2;" : "=f"(lo), "=f"(hi) : "l"(v));
}
__device__ __forceinline__ u64 dupf(float x) {
    u64 d; asm("mov.b64 %0, {%1, %1};" : "=l"(d) : "f"(x));
    return d;
}
// exact leaky-relu(0.01): max(x, 0.01*x)
__device__ __forceinline__ u64 lrelu2(u64 x, u64 c001) {
    u64 m = mul2(x, c001);
    float2 xf = *(float2*)&x, mf = *(float2*)&m, r;
    r.x = fmaxf(xf.x, mf.x);
    r.y = fmaxf(xf.y, mf.y);
    return *(u64*)&r;
}

__global__ void __launch_bounds__(NTHR, 1) rnn_kernel(
    const float* __restrict__ inputs,
    const float* __restrict__ w1,  const float* __restrict__ b1,
    const float* __restrict__ w2,  const float* __restrict__ b2,
    const float* __restrict__ ow1, const float* __restrict__ ob1,
    const float* __restrict__ ow2, const float* __restrict__ ob2,
    float* __restrict__ outp)
{
    // fused weights [M; N] (80 j x 40 k) non-dup: [kq][j] float4 (4 k's)
    __shared__ __align__(16) float fWA[10 * 80 * 4];   // 12800 B
    __shared__ __align__(16) float sW2f[40 * 40];      //  6400 B (prologue)
    __shared__ __align__(16) u64 sZ[2 * 2 * 42];       // [buf][pair][42]; [40]=u
    __shared__ __align__(16) u64 sOutP[2 * 2 * 8];     // [buf][pair][8]

    const int tid = threadIdx.x;
    const int baseRow = blockIdx.x * 4;
    const int s1 = tid & 1, jg1 = tid >> 1;    // pair, neuron-group (5 neurons)
    const bool isH2H = (jg1 < 8);
    const int j0 = 5 * jg1;                    // global neuron base (0..75)
    const u64 c001 = dupf(0.01f);

    // ---- stage w2 ----
    for (int idx = tid; idx < 1600; idx += NTHR) sW2f[idx] = w2[idx];
    __syncwarp();

    // global pointer to this thread's 5 rows of the L1 hidden block (stride 41)
    const float* wrow = isH2H ? (w1 + j0 * 41 + 1)
                              : (ow1 + (j0 - 40) * 41 + 1);

    // ---- prologue: fused M/N = W1h @ W2 -> fWA (s1==0 twin computes) ----
    if (s1 == 0) {
        for (int pass = 0; pass < 4; pass++) {
            const int k0 = 10 * pass;
            u64 acc2[5][5];
#pragma unroll
            for (int i = 0; i < 5; i++)
#pragma unroll
                for (int q = 0; q < 5; q++) acc2[i][q] = 0ull;
            for (int m = 0; m < 40; m++) {
                u64 a[5];
#pragma unroll
                for (int i = 0; i < 5; i++) a[i] = dupf(wrow[i * 41 + m]);
                const u64* wv2 = (const u64*)(sW2f + m * 40 + k0);
#pragma unroll
                for (int q = 0; q < 5; q++) {
                    u64 wv = wv2[q];
#pragma unroll
                    for (int i = 0; i < 5; i++)
                        acc2[i][q] = fma2(a[i], wv, acc2[i][q]);
                }
            }
#pragma unroll
            for (int i = 0; i < 5; i++)
#pragma unroll
                for (int q = 0; q < 5; q++) {
                    float lo, hi; unpack2(acc2[i][q], lo, hi);
                    int k = k0 + 2 * q;
                    fWA[((k >> 2) * 80 + (j0 + i)) * 4 + (k & 3)] = lo;
                    k++;
                    fWA[((k >> 2) * 80 + (j0 + i)) * 4 + (k & 3)] = hi;
                }
        }
    }

    // ---- fused biases c/d, u-weights (registers), out-dot weights ----
    u64 bA[5], rW[5], wu[5];
    {
        float cd[5] = {0, 0, 0, 0, 0};
        for (int m = 0; m < 40; m++) {
            float bv = b2[m];
#pragma unroll
            for (int i = 0; i < 5; i++) cd[i] += wrow[i * 41 + m] * bv;
        }
#pragma unroll
        for (int i = 0; i < 5; i++) {
            float base = isH2H ? b1[j0 + i] : ob1[j0 - 40 + i];
            bA[i] = dupf(cd[i] + base);
            rW[i] = isH2H ? 0ull : dupf(ow2[j0 - 40 + i]);
            wu[i] = dupf(isH2H ? w1[(j0 + i) * 41] : ow1[(j0 - 40 + i) * 41]);
        }
    }
    const u64 bo = dupf(ob2[0]);
    __syncwarp();   // fWA visible to all lanes

    // ---- register slice of fused weights: k = 0..19 (100 floats) ----
    float wreg[5][20];
#pragma unroll
    for (int i = 0; i < 5; i++)
#pragma unroll
        for (int q = 0; q < 20; q++)
            wreg[i][q] = fWA[((q >> 2) * 80 + (j0 + i)) * 4 + (q & 3)];

    // ---- special step t = 0 (h = 0: plain biases, u-column only) ----
    {
        const int pr0 = baseRow + 2 * s1, pr1 = pr0 + 1;
        u64 u0 = pack2(inputs[(size_t)pr0 * Tn], inputs[(size_t)pr1 * Tn]);
        u64 z[5];
#pragma unroll
        for (int i = 0; i < 5; i++) {
            float pbv = isH2H ? b1[j0 + i] : ob1[j0 - 40 + i];
            z[i] = lrelu2(fma2(u0, wu[i], dupf(pbv)), c001);
        }
        if (isH2H) {
            u64* d = sZ + s1 * 42 + j0;
#pragma unroll
            for (int i = 0; i < 5; i++) d[i] = z[i];
        } else {
            u64 p = mul2(z[0], rW[0]);
            p = fma2(z[1], rW[1], p); p = fma2(z[2], rW[2], p);
            p = fma2(z[3], rW[3], p); p = fma2(z[4], rW[4], p);
            sOutP[s1 * 8 + (jg1 - 8)] = p;
        }
        if (tid < 2)   // u(1) into buffer 0
            sZ[tid * 42 + 40] = pack2(inputs[(size_t)(baseRow + 2 * tid) * Tn + 1],
                                      inputs[(size_t)(baseRow + 2 * tid + 1) * Tn + 1]);
    }
    __syncwarp();

    // ---- main loop t = 1 .. 1023 ----
    const float4* wA4 = (const float4*)fWA + jg1 * 5;
    const int r0 = baseRow + 2 * tid;          // rows for tid<2 duties
    const int r1v = r0 + 1;
    int cur = 0;
    for (int t = 1; t < Tn; t++) {
        // issue next-input LDG at the very top (hidden under the GEMV)
        u64 uN = 0ull;
        if (tid < 2 && t + 1 < Tn)
            uN = pack2(inputs[(size_t)r0 * Tn + t + 1],
                       inputs[(size_t)r1v * Tn + t + 1]);

        // reduce out(t-1) from previous step's partials
        if (tid < 2) {
            const ulonglong2* pp = (const ulonglong2*)(sOutP + cur * 16 + tid * 8);
            ulonglong2 p0 = pp[0], p1 = pp[1], p2 = pp[2], p3 = pp[3];
            u64 s = add2(add2(add2(p0.x, p0.y), add2(p1.x, p1.y)),
                         add2(add2(p2.x, p2.y), add2(p3.x, p3.y)));
            s = add2(s, bo);
            float lo, hi; unpack2(s, lo, hi);
            outp[(size_t)r0 * Tn + (t - 1)] = lo;
            outp[(size_t)r1v * Tn + (t - 1)] = hi;
        }

        const u64* zb = sZ + cur * 84 + s1 * 42;
        u64 a0 = bA[0], a1 = bA[1], a2 = bA[2], a3 = bA[3], a4 = bA[4];

        // ---- front-loaded LDS: part-1 z (k0..19), u, and 2 pipeline stages ----
        ulonglong2 y0 = *(const ulonglong2*)(zb + 0);
        ulonglong2 y1 = *(const ulonglong2*)(zb + 2);
        ulonglong2 y2 = *(const ulonglong2*)(zb + 4);
        ulonglong2 y3 = *(const ulonglong2*)(zb + 6);
        ulonglong2 y4 = *(const ulonglong2*)(zb + 8);
        ulonglong2 y5 = *(const ulonglong2*)(zb + 10);
        ulonglong2 y6 = *(const ulonglong2*)(zb + 12);
        ulonglong2 y7 = *(const ulonglong2*)(zb + 14);
        ulonglong2 y8 = *(const ulonglong2*)(zb + 16);
        ulonglong2 y9 = *(const ulonglong2*)(zb + 18);
        u64 ua = zb[40];
        // depth-2 pipeline stages for shared part (kq = 5, 6)
        ulonglong2 qz01[2], qz23[2];
        float4 qv0[2], qv1[2], qv2[2], qv3[2], qv4[2];
#pragma unroll
        for (int s = 0; s < 2; s++) {
            qz01[s] = *(const ulonglong2*)(zb + 4 * (5 + s));
            qz23[s] = *(const ulonglong2*)(zb + 4 * (5 + s) + 2);
            qv0[s] = wA4[(5 + s) * 80 + 0];
            qv1[s] = wA4[(5 + s) * 80 + 1];
            qv2[s] = wA4[(5 + s) * 80 + 2];
            qv3[s] = wA4[(5 + s) * 80 + 3];
            qv4[s] = wA4[(5 + s) * 80 + 4];
        }

        // ---- part 1: k = 0..19 from register weights (no LDS deps) ----
#pragma unroll
        for (int i = 0; i < 5; i++) {
            u64 a = (i == 0) ? a0 : (i == 1) ? a1 : (i == 2) ? a2
                                  : (i == 3) ? a3 : a4;
            a = fma2(y0.x, dupf(wreg[i][0]),  a);
            a = fma2(y0.y, dupf(wreg[i][1]),  a);
            a = fma2(y1.x, dupf(wreg[i][2]),  a);
            a = fma2(y1.y, dupf(wreg[i][3]),  a);
            a = fma2(y2.x, dupf(wreg[i][4]),  a);
            a = fma2(y2.y, dupf(wreg[i][5]),  a);
            a = fma2(y3.x, dupf(wreg[i][6]),  a);
            a = fma2(y3.y, dupf(wreg[i][7]),  a);
            a = fma2(y4.x, dupf(wreg[i][8]),  a);
            a = fma2(y4.y, dupf(wreg[i][9]),  a);
            a = fma2(y5.x, dupf(wreg[i][10]), a);
            a = fma2(y5.y, dupf(wreg[i][11]), a);
            a = fma2(y6.x, dupf(wreg[i][12]), a);
            a = fma2(y6.y, dupf(wreg[i][13]), a);
            a = fma2(y7.x, dupf(wreg[i][14]), a);
            a = fma2(y7.y, dupf(wreg[i][15]), a);
            a = fma2(y8.x, dupf(wreg[i][16]), a);
            a = fma2(y8.y, dupf(wreg[i][17]), a);
            a = fma2(y9.x, dupf(wreg[i][18]), a);
            a = fma2(y9.y, dupf(wreg[i][19]), a);
            if (i == 0) a0 = a; else if (i == 1) a1 = a; else if (i == 2) a2 = a;
            else if (i == 3) a3 = a; else a4 = a;
        }

        // ---- part 2: kq = 5..9 from shared, depth-2 pipelined ----
#pragma unroll
        for (int kq = 5; kq < 10; kq++) {
            const int sl = (kq - 5) & 1;
            ulonglong2 cz01 = qz01[sl], cz23 = qz23[sl];
            float4 c0 = qv0[sl], c1 = qv1[sl], c2 = qv2[sl],
                   c3 = qv3[sl], c4 = qv4[sl];
            if (kq + 2 < 10) {   // refill this slot 2 iterations ahead
                qz01[sl] = *(const ulonglong2*)(zb + 4 * (kq + 2));
                qz23[sl] = *(const ulonglong2*)(zb + 4 * (kq + 2) + 2);
                qv0[sl] = wA4[(kq + 2) * 80 + 0];
                qv1[sl] = wA4[(kq + 2) * 80 + 1];
                qv2[sl] = wA4[(kq + 2) * 80 + 2];
                qv3[sl] = wA4[(kq + 2) * 80 + 3];
                qv4[sl] = wA4[(kq + 2) * 80 + 4];
            }
            u64 dx;
            dx = dupf(c0.x); a0 = fma2(cz01.x, dx, a0);
            dx = dupf(c0.y); a0 = fma2(cz01.y, dx, a0);
            dx = dupf(c0.z); a0 = fma2(cz23.x, dx, a0);
            dx = dupf(c0.w); a0 = fma2(cz23.y, dx, a0);
            dx = dupf(c1.x); a1 = fma2(cz01.x, dx, a1);
            dx = dupf(c1.y); a1 = fma2(cz01.y, dx, a1);
            dx = dupf(c1.z); a1 = fma2(cz23.x, dx, a1);
            dx = dupf(c1.w); a1 = fma2(cz23.y, dx, a1);
            dx = dupf(c2.x); a2 = fma2(cz01.x, dx, a2);
            dx = dupf(c2.y); a2 = fma2(cz01.y, dx, a2);
            dx = dupf(c2.z); a2 = fma2(cz23.x, dx, a2);
            dx = dupf(c2.w); a2 = fma2(cz23.y, dx, a2);
            dx = dupf(c3.x); a3 = fma2(cz01.x, dx, a3);
            dx = dupf(c3.y); a3 = fma2(cz01.y, dx, a3);
            dx = dupf(c3.z); a3 = fma2(cz23.x, dx, a3);
            dx = dupf(c3.w); a3 = fma2(cz23.y, dx, a3);
            dx = dupf(c4.x); a4 = fma2(cz01.x, dx, a4);
            dx = dupf(c4.y); a4 = fma2(cz01.y, dx, a4);
            dx = dupf(c4.z); a4 = fma2(cz23.x, dx, a4);
            dx = dupf(c4.w); a4 = fma2(cz23.y, dx, a4);
        }
        {   // u-term (ua loaded at step top, weights in registers)
            a0 = fma2(ua, wu[0], a0);
            a1 = fma2(ua, wu[1], a1);
            a2 = fma2(ua, wu[2], a2);
            a3 = fma2(ua, wu[3], a3);
            a4 = fma2(ua, wu[4], a4);
        }
        a0 = lrelu2(a0, c001);
        a1 = lrelu2(a1, c001);
        a2 = lrelu2(a2, c001);
        a3 = lrelu2(a3, c001);
        a4 = lrelu2(a4, c001);

        const int nxt = cur ^ 1;
        if (isH2H) {  // a(t) -> next buffer
            u64* d = sZ + nxt * 84 + s1 * 42 + j0;
            d[0] = a0; d[1] = a1; d[2] = a2; d[3] = a3; d[4] = a4;
        } else {      // o(t) -> out-dot partials (reduced next step)
            u64 p = mul2(a0, rW[0]);
            p = fma2(a1, rW[1], p); p = fma2(a2, rW[2], p);
            p = fma2(a3, rW[3], p); p = fma2(a4, rW[4], p);
            sOutP[nxt * 16 + s1 * 8 + (jg1 - 8)] = p;
        }
        if (tid < 2)   // u(t+1) into next buffer
            sZ[nxt * 84 + tid * 42 + 40] = uN;
        __syncwarp();
        cur = nxt;
    }

    // final out(1023)
    if (tid < 2) {
        const ulonglong2* pp = (const ulonglong2*)(sOutP + cur * 16 + tid * 8);
        ulonglong2 p0 = pp[0], p1 = pp[1], p2 = pp[2], p3 = pp[3];
        u64 s = add2(add2(add2(p0.x, p0.y), add2(p1.x, p1.y)),
                     add2(add2(p2.x, p2.y), add2(p3.x, p3.y)));
        s = add2(s, bo);
        float lo, hi; unpack2(s, lo, hi);
        outp[(size_t)r0 * Tn + (Tn - 1)] = lo;
        outp[(size_t)r1v * Tn + (Tn - 1)] = hi;
    }
}

extern "C" void kernel_launch(void* const* d_in, const int* in_sizes, int n_in,
                              void* d_out, int out_size) {
    const float* inputs = (const float*)d_in[0];
    const float* w1  = (const float*)d_in[1];
    const float* b1  = (const float*)d_in[2];
    const float* w2  = (const float*)d_in[3];
    const float* b2  = (const float*)d_in[4];
    const float* ow1 = (const float*)d_in[5];
    const float* ob1 = (const float*)d_in[6];
    const float* ow2 = (const float*)d_in[7];
    const float* ob2 = (const float*)d_in[8];
    float* out = (float*)d_out;

    rnn_kernel<<<NBLK, NTHR>>>(inputs, w1, b1, w2, b2,
                               ow1, ob1, ow2, ob2, out);
}